// round 6
// baseline (speedup 1.0000x reference)
#include <cuda_runtime.h>
#include <cstdint>

#define BB   16
#define CC   32
#define HH   256
#define WW   256
#define T2   8
#define NT   (2*T2)
#define NHC  32               // half-chunks (8 rows each)
#define FIELD (HH*WW)
#define BT   (BB*T2)

typedef unsigned long long u64;

// ---------------- scratch (no cudaMalloc allowed) ----------------
__device__ __align__(256) float g_w1 [BT*FIELD];
__device__ __align__(256) float g_gv2[BT*FIELD];
__device__ __align__(256) float g_Sh [BT*3*NHC*WW];   // halfchunk colsums (w3,w3p,w2p)
__device__ __align__(256) float g_S3 [BT*NHC*WW];     // halfchunk colsums of gv2
__device__ u64 g_apk[T2*6*CC];                        // packed alphas (staging)
__constant__ u64 c_al[T2*6*CC];                       // packed alphas (uniform const loads)

// ---------------- f32x2 helpers ----------------
__device__ __forceinline__ u64 fma2(u64 a, u64 b, u64 c) {
    u64 d; asm("fma.rn.f32x2 %0, %1, %2, %3;" : "=l"(d) : "l"(a), "l"(b), "l"(c)); return d;
}
__device__ __forceinline__ u64 add2(u64 a, u64 b) {
    u64 d; asm("add.rn.f32x2 %0, %1, %2;" : "=l"(d) : "l"(a), "l"(b)); return d;
}
__device__ __forceinline__ u64 pack2(float lo, float hi) {
    u64 r; asm("mov.b64 %0, {%1, %2};" : "=l"(r) : "f"(lo), "f"(hi)); return r;
}
__device__ __forceinline__ float2 unpack2(u64 v) {
    float2 f; asm("mov.b64 {%0, %1}, %2;" : "=f"(f.x), "=f"(f.y) : "l"(v)); return f;
}

// ---------------- warp scan: 256 elems, 8 per lane ----------------
__device__ __forceinline__ float wscan8(const float* v, float* incl) {
    float r = 0.f; float tmp[8];
    #pragma unroll
    for (int i = 0; i < 8; i++) { r += v[i]; tmp[i] = r; }
    float s = r;
    const int lane = threadIdx.x & 31;
    #pragma unroll
    for (int d = 1; d < 32; d <<= 1) {
        float n = __shfl_up_sync(0xffffffffu, s, d);
        if (lane >= d) s += n;
    }
    float excl = s - r;
    #pragma unroll
    for (int i = 0; i < 8; i++) incl[i] = tmp[i] + excl;
    return __shfl_sync(0xffffffffu, s, 31);
}

__device__ __forceinline__ void LD8(float* v, const float* p) {
    float4 a = *(const float4*)p, b = *(const float4*)(p + 4);
    v[0]=a.x; v[1]=a.y; v[2]=a.z; v[3]=a.w; v[4]=b.x; v[5]=b.y; v[6]=b.z; v[7]=b.w;
}
__device__ __forceinline__ void ST8(float* p, const float* v) {
    *(float4*)p       = make_float4(v[0],v[1],v[2],v[3]);
    *(float4*)(p + 4) = make_float4(v[4],v[5],v[6],v[7]);
}

// =====================================================================
// K0: pack alphas duplicated into f32x2 pairs (staging for c_al)
// field order: 0=a1 1=a2 2=a3 3=a1p 4=a2p 5=a3p
// =====================================================================
__global__ void k0_pack(const float* __restrict__ a1,  const float* __restrict__ a2,
                        const float* __restrict__ a3,  const float* __restrict__ a1p,
                        const float* __restrict__ a2p, const float* __restrict__ a3p)
{
    int i = blockIdx.x * 256 + threadIdx.x;          // T2*6*CC = 1536
    if (i >= T2 * 6 * CC) return;
    int c = i % CC, f = (i / CC) % 6, t = i / (6 * CC);
    const float* p = (f == 0) ? a1 : (f == 1) ? a2 : (f == 2) ? a3
                   : (f == 3) ? a1p : (f == 4) ? a2p : a3p;
    float v = p[t * CC + c];
    g_apk[(t * 6 + f) * CC + c] = pack2(v, v);
}

// =====================================================================
// KAB: Sh directly from x. colsum_h(w_k) = alpha_k . colsum_h(x).
// grid = (NHC, BB), 128 thr, 2 cols/thread.
// =====================================================================
__global__ void __launch_bounds__(128) kAB_colsum(const float* __restrict__ x)
{
    const int tid = threadIdx.x;
    const int hc  = blockIdx.x;
    const int b   = blockIdx.y;
    const int wc  = tid * 2;

    u64 acc[T2][3];
    #pragma unroll
    for (int t = 0; t < T2; t++)
        #pragma unroll
        for (int k = 0; k < 3; k++) acc[t][k] = 0ull;

    #pragma unroll 2
    for (int c = 0; c < CC; c++) {
        const float2* xp = (const float2*)(x
            + ((size_t)(b * CC + c) * HH + hc * 8) * WW + wc);
        u64 sum = 0ull;
        #pragma unroll
        for (int r = 0; r < 8; r++) {
            float2 v = xp[r * (WW / 2)];
            sum = add2(sum, pack2(v.x, v.y));
        }
        #pragma unroll
        for (int t = 0; t < T2; t++) {
            acc[t][0] = fma2(sum, c_al[(t * 6 + 2) * CC + c], acc[t][0]); // w3
            acc[t][1] = fma2(sum, c_al[(t * 6 + 5) * CC + c], acc[t][1]); // w3p
            acc[t][2] = fma2(sum, c_al[(t * 6 + 4) * CC + c], acc[t][2]); // w2p
        }
    }

    #pragma unroll
    for (int t = 0; t < T2; t++)
        #pragma unroll
        for (int k = 0; k < 3; k++) {
            float2 v = unpack2(acc[t][k]);
            size_t o = (((size_t)(b * T2 + t) * 3 + k) * NHC + hc) * WW + wc;
            *(float2*)&g_Sh[o] = v;
        }
}

// =====================================================================
// KC: fused weighting + bottom-up pass. One warp per (tree, hc, b).
// Recomputes all 6 fields from x in registers; emits cherry (out),
// gv2, w1, and S3 (halfchunk colsums of gv2).
// grid = (2, NHC, BB), 128 thr = 4 warps = 4 trees.
// =====================================================================
__global__ void __launch_bounds__(128, 4) kC_fused(const float* __restrict__ x,
                                                   float* __restrict__ out)
{
    const int wid  = threadIdx.x >> 5;
    const int lane = threadIdx.x & 31;
    const int t    = blockIdx.x * 4 + wid;
    const int hc   = blockIdx.y;
    const int b    = blockIdx.z;
    const int bt   = b * T2 + t;
    const int col  = lane * 8;

    // init states from Sh of halfchunks strictly below
    float s0[8], s1[8], s2[8];
    #pragma unroll
    for (int i = 0; i < 8; i++) { s0[i] = 0.f; s1[i] = 0.f; s2[i] = 0.f; }
    for (int j = hc + 1; j < NHC; j++) {
        const size_t o = (size_t)bt * 3 * NHC * WW + (size_t)j * WW + col;
        float v[8];
        LD8(v, g_Sh + o);
        #pragma unroll
        for (int i = 0; i < 8; i++) s0[i] += v[i];
        LD8(v, g_Sh + o + (size_t)NHC * WW);
        #pragma unroll
        for (int i = 0; i < 8; i++) s1[i] += v[i];
        LD8(v, g_Sh + o + 2 * (size_t)NHC * WW);
        #pragma unroll
        for (int i = 0; i < 8; i++) s2[i] += v[i];
    }

    float a3[8], p3[8], p2[8], incl[8];
    {
        wscan8(s0, incl);
        #pragma unroll
        for (int i = 0; i < 8; i++) a3[i] = incl[i] - s0[i];
        wscan8(s1, incl);
        #pragma unroll
        for (int i = 0; i < 8; i++) p3[i] = incl[i] - s1[i];
        float tot = wscan8(s2, incl);
        #pragma unroll
        for (int i = 0; i < 8; i++) p2[i] = tot - incl[i];
    }

    float cssum[8];
    #pragma unroll
    for (int i = 0; i < 8; i++) cssum[i] = 0.f;

    #pragma unroll 1
    for (int r = 7; r >= 0; r--) {
        const int h = hc * 8 + r;

        // ---- weighting: all 6 fields for this row, 8 cols/lane ----
        u64 acc[6][4];
        #pragma unroll
        for (int f = 0; f < 6; f++)
            #pragma unroll
            for (int j = 0; j < 4; j++) acc[f][j] = 0ull;

        const float4* xq = (const float4*)(x + (size_t)b * CC * FIELD
                                             + (size_t)h * WW + col);
        #pragma unroll 4
        for (int c = 0; c < CC; c++) {
            float4 v0 = xq[(size_t)c * (FIELD / 4)];
            float4 v1 = xq[(size_t)c * (FIELD / 4) + 1];
            u64 xx0 = pack2(v0.x, v0.y), xx1 = pack2(v0.z, v0.w);
            u64 xx2 = pack2(v1.x, v1.y), xx3 = pack2(v1.z, v1.w);
            #pragma unroll
            for (int f = 0; f < 6; f++) {
                u64 al = c_al[(t * 6 + f) * CC + c];   // warp-uniform const
                acc[f][0] = fma2(xx0, al, acc[f][0]);
                acc[f][1] = fma2(xx1, al, acc[f][1]);
                acc[f][2] = fma2(xx2, al, acc[f][2]);
                acc[f][3] = fma2(xx3, al, acc[f][3]);
            }
        }

        const size_t base = (size_t)bt * FIELD + (size_t)h * WW + col;
        float tmp[8];

        // v2 = w2 * a3 (strict-below state); gv2 = rev-excl-w-scan(v2)
        #pragma unroll
        for (int j = 0; j < 4; j++) {
            float2 v = unpack2(acc[1][j]); tmp[2*j] = v.x; tmp[2*j+1] = v.y;
        }
        #pragma unroll
        for (int i = 0; i < 8; i++) tmp[i] *= a3[i];
        float tot = wscan8(tmp, incl);
        #pragma unroll
        for (int i = 0; i < 8; i++) { tmp[i] = tot - incl[i]; cssum[i] += tmp[i]; }
        ST8(g_gv2 + base, tmp);

        // w1 store
        #pragma unroll
        for (int j = 0; j < 4; j++) {
            float2 v = unpack2(acc[0][j]); tmp[2*j] = v.x; tmp[2*j+1] = v.y;
        }
        ST8(g_w1 + base, tmp);

        // cherry = w1p * p3 * p2 (strict-below states)
        #pragma unroll
        for (int j = 0; j < 4; j++) {
            float2 v = unpack2(acc[3][j]); tmp[2*j] = v.x; tmp[2*j+1] = v.y;
        }
        #pragma unroll
        for (int i = 0; i < 8; i++) tmp[i] *= p3[i] * p2[i];
        ST8(out + ((size_t)(b * NT + T2 + t)) * FIELD + (size_t)h * WW + col, tmp);

        // state updates with this row's fields
        #pragma unroll
        for (int j = 0; j < 4; j++) {
            float2 v = unpack2(acc[2][j]); tmp[2*j] = v.x; tmp[2*j+1] = v.y;
        }
        wscan8(tmp, incl);
        #pragma unroll
        for (int i = 0; i < 8; i++) a3[i] += incl[i] - tmp[i];     // fwd-excl(w3)

        #pragma unroll
        for (int j = 0; j < 4; j++) {
            float2 v = unpack2(acc[5][j]); tmp[2*j] = v.x; tmp[2*j+1] = v.y;
        }
        wscan8(tmp, incl);
        #pragma unroll
        for (int i = 0; i < 8; i++) p3[i] += incl[i] - tmp[i];     // fwd-excl(w3p)

        #pragma unroll
        for (int j = 0; j < 4; j++) {
            float2 v = unpack2(acc[4][j]); tmp[2*j] = v.x; tmp[2*j+1] = v.y;
        }
        tot = wscan8(tmp, incl);
        #pragma unroll
        for (int i = 0; i < 8; i++) p2[i] += tot - incl[i];        // rev-excl(w2p)
    }

    ST8(g_S3 + ((size_t)bt * NHC + hc) * WW + col, cssum);
}

// =====================================================================
// KD: top-down. linear = w1 * strict-north colsum of gv2.
// One warp per (halfchunk,t,b); double-buffered row prefetch.
// =====================================================================
__global__ void __launch_bounds__(128) kD_topdown(float* __restrict__ out)
{
    const int wid  = threadIdx.x >> 5;
    const int lane = threadIdx.x & 31;
    const int gw   = blockIdx.x * 4 + wid;
    const int half =  gw        & 31;
    const int t    = (gw >> 5)  & 7;
    const int b    =  gw >> 8;
    const int bt   = b * T2 + t;
    const int col  = lane * 8;

    float va[8];
    #pragma unroll
    for (int i = 0; i < 8; i++) va[i] = 0.f;
    for (int j = 0; j < half; j++) {
        const float* p = g_S3 + ((size_t)bt * NHC + j) * WW + col;
        float4 a = *(const float4*)p, bq = *(const float4*)(p + 4);
        va[0] += a.x;  va[1] += a.y;  va[2] += a.z;  va[3] += a.w;
        va[4] += bq.x; va[5] += bq.y; va[6] += bq.z; va[7] += bq.w;
    }

    const size_t fbase = (size_t)bt * FIELD + (size_t)(half * 8) * WW + col;
    const size_t obase = ((size_t)(b * NT + t)) * FIELD + (size_t)(half * 8) * WW + col;

    float w1b[8], gvb[8];
    LD8(w1b, g_w1 + fbase);
    LD8(gvb, g_gv2 + fbase);

    #pragma unroll
    for (int r = 0; r < 8; r++) {
        float w1n[8], gvn[8];
        if (r < 7) {
            LD8(w1n, g_w1  + fbase + (size_t)(r + 1) * WW);
            LD8(gvn, g_gv2 + fbase + (size_t)(r + 1) * WW);
        }
        float o[8];
        #pragma unroll
        for (int i = 0; i < 8; i++) o[i] = w1b[i] * va[i];
        ST8(out + obase + (size_t)r * WW, o);
        #pragma unroll
        for (int i = 0; i < 8; i++) va[i] += gvb[i];
        if (r < 7) {
            #pragma unroll
            for (int i = 0; i < 8; i++) { w1b[i] = w1n[i]; gvb[i] = gvn[i]; }
        }
    }
}

// =====================================================================
extern "C" void kernel_launch(void* const* d_in, const int* in_sizes, int n_in,
                              void* d_out, int out_size)
{
    const float* x   = (const float*)d_in[0];
    const float* a1  = (const float*)d_in[1];
    const float* a2  = (const float*)d_in[2];
    const float* a3  = (const float*)d_in[3];
    const float* a1p = (const float*)d_in[4];
    const float* a2p = (const float*)d_in[5];
    const float* a3p = (const float*)d_in[6];
    float* out = (float*)d_out;

    k0_pack<<<6, 256>>>(a1, a2, a3, a1p, a2p, a3p);

    void* src = nullptr; void* dst = nullptr;
    cudaGetSymbolAddress(&src, g_apk);
    cudaGetSymbolAddress(&dst, c_al);
    cudaMemcpyAsync(dst, src, sizeof(u64) * T2 * 6 * CC,
                    cudaMemcpyDeviceToDevice, 0);

    dim3 gAB(NHC, BB);                    // (32, 16)
    kAB_colsum<<<gAB, 128>>>(x);

    dim3 gC(2, NHC, BB);                  // (2, 32, 16) = 1024 CTAs
    kC_fused<<<gC, 128>>>(x, out);

    kD_topdown<<<BT * NHC / 4, 128>>>(out);
}

// round 7
// speedup vs baseline: 1.8551x; 1.8551x over previous
#include <cuda_runtime.h>
#include <cstdint>

#define BB   16
#define CC   32
#define HH   256
#define WW   256
#define T2   8
#define NT   (2*T2)
#define NHC  32               // half-chunks (8 rows each)
#define FIELD (HH*WW)
#define BT   (BB*T2)

typedef unsigned long long u64;

// ---------------- scratch (no cudaMalloc allowed) ----------------
__device__ __align__(256) float g_w1 [BT*FIELD];
__device__ __align__(256) float g_w2 [BT*FIELD];
__device__ __align__(256) float g_w3 [BT*FIELD];
__device__ __align__(256) float g_w1p[BT*FIELD];
__device__ __align__(256) float g_w2p[BT*FIELD];
__device__ __align__(256) float g_w3p[BT*FIELD];
__device__ __align__(256) float g_gv2[BT*FIELD];
__device__ __align__(256) float g_Sh [BT*3*NHC*WW];   // halfchunk colsums (w3,w3p,w2p)
__device__ __align__(256) float g_S3 [BT*NHC*WW];     // halfchunk colsums of gv2
__device__ u64 g_apk[T2*6*CC];                        // packed alphas (staging)
__constant__ u64 c_al[T2*6*CC];                       // packed alphas

// ---------------- f32x2 helpers ----------------
__device__ __forceinline__ u64 fma2(u64 a, u64 b, u64 c) {
    u64 d; asm("fma.rn.f32x2 %0, %1, %2, %3;" : "=l"(d) : "l"(a), "l"(b), "l"(c)); return d;
}
__device__ __forceinline__ u64 add2(u64 a, u64 b) {
    u64 d; asm("add.rn.f32x2 %0, %1, %2;" : "=l"(d) : "l"(a), "l"(b)); return d;
}
__device__ __forceinline__ u64 pack2(float lo, float hi) {
    u64 r; asm("mov.b64 %0, {%1, %2};" : "=l"(r) : "f"(lo), "f"(hi)); return r;
}
__device__ __forceinline__ float2 unpack2(u64 v) {
    float2 f; asm("mov.b64 {%0, %1}, %2;" : "=f"(f.x), "=f"(f.y) : "l"(v)); return f;
}

// ---------------- warp scan: 256 elems, 8 per lane ----------------
__device__ __forceinline__ float wscan8(const float* v, float* incl) {
    float r = 0.f; float tmp[8];
    #pragma unroll
    for (int i = 0; i < 8; i++) { r += v[i]; tmp[i] = r; }
    float s = r;
    const int lane = threadIdx.x & 31;
    #pragma unroll
    for (int d = 1; d < 32; d <<= 1) {
        float n = __shfl_up_sync(0xffffffffu, s, d);
        if (lane >= d) s += n;
    }
    float excl = s - r;
    #pragma unroll
    for (int i = 0; i < 8; i++) incl[i] = tmp[i] + excl;
    return __shfl_sync(0xffffffffu, s, 31);
}

__device__ __forceinline__ void LD8(float* v, const float* p) {
    float4 a = *(const float4*)p, b = *(const float4*)(p + 4);
    v[0]=a.x; v[1]=a.y; v[2]=a.z; v[3]=a.w; v[4]=b.x; v[5]=b.y; v[6]=b.z; v[7]=b.w;
}
__device__ __forceinline__ void ST8(float* p, const float* v) {
    *(float4*)p       = make_float4(v[0],v[1],v[2],v[3]);
    *(float4*)(p + 4) = make_float4(v[4],v[5],v[6],v[7]);
}

// =====================================================================
// K0: pack alphas duplicated into f32x2 pairs (staging for c_al)
// field order: 0=a1 1=a2 2=a3 3=a1p 4=a2p 5=a3p
// =====================================================================
__global__ void k0_pack(const float* __restrict__ a1,  const float* __restrict__ a2,
                        const float* __restrict__ a3,  const float* __restrict__ a1p,
                        const float* __restrict__ a2p, const float* __restrict__ a3p)
{
    int i = blockIdx.x * 256 + threadIdx.x;          // T2*6*CC = 1536
    if (i >= T2 * 6 * CC) return;
    int c = i % CC, f = (i / CC) % 6, t = i / (6 * CC);
    const float* p = (f == 0) ? a1 : (f == 1) ? a2 : (f == 2) ? a3
                   : (f == 3) ? a1p : (f == 4) ? a2p : a3p;
    float v = p[t * CC + c];
    g_apk[(t * 6 + f) * CC + c] = pack2(v, v);
}

// =====================================================================
// KAB: Sh directly from x. colsum_h(w_k) = alpha_k . colsum_h(x).
// (validated in R6) grid = (NHC, BB), 128 thr, 2 cols/thread.
// =====================================================================
__global__ void __launch_bounds__(128) kAB_colsum(const float* __restrict__ x)
{
    const int tid = threadIdx.x;
    const int hc  = blockIdx.x;
    const int b   = blockIdx.y;
    const int wc  = tid * 2;

    u64 acc[T2][3];
    #pragma unroll
    for (int t = 0; t < T2; t++)
        #pragma unroll
        for (int k = 0; k < 3; k++) acc[t][k] = 0ull;

    #pragma unroll 2
    for (int c = 0; c < CC; c++) {
        const float2* xp = (const float2*)(x
            + ((size_t)(b * CC + c) * HH + hc * 8) * WW + wc);
        u64 sum = 0ull;
        #pragma unroll
        for (int r = 0; r < 8; r++) {
            float2 v = xp[r * (WW / 2)];
            sum = add2(sum, pack2(v.x, v.y));
        }
        #pragma unroll
        for (int t = 0; t < T2; t++) {
            acc[t][0] = fma2(sum, c_al[(t * 6 + 2) * CC + c], acc[t][0]); // w3
            acc[t][1] = fma2(sum, c_al[(t * 6 + 5) * CC + c], acc[t][1]); // w3p
            acc[t][2] = fma2(sum, c_al[(t * 6 + 4) * CC + c], acc[t][2]); // w2p
        }
    }

    #pragma unroll
    for (int t = 0; t < T2; t++)
        #pragma unroll
        for (int k = 0; k < 3; k++) {
            float2 v = unpack2(acc[t][k]);
            size_t o = (((size_t)(b * T2 + t) * 3 + k) * NHC + hc) * WW + wc;
            *(float2*)&g_Sh[o] = v;
        }
}

// =====================================================================
// K1: weighting GEMM only. 8 cols/thread -> 48 FFMA2 per 12 LDC per
// channel (2x better constant-port ratio than R5). No colsums here.
// 128 thr: rg = tid>>5 (4 rows), 32 lanes x 8 cols. 2 row-batches.
// grid = (T2/2, NHC, BB) = 2048 CTAs.
// =====================================================================
__global__ void __launch_bounds__(128) k1_weight(const float* __restrict__ x)
{
    const int tid  = threadIdx.x;
    const int rg   = tid >> 5;           // 0..3
    const int lane = tid & 31;
    const int col  = lane * 8;
    const int t0   = blockIdx.x * 2;
    const int hc   = blockIdx.y;
    const int b    = blockIdx.z;
    const int bt0  = b * T2 + t0;

    #pragma unroll 1
    for (int it = 0; it < 2; it++) {
        const int h = hc * 8 + it * 4 + rg;

        u64 acc[2][6][4];
        #pragma unroll
        for (int tr = 0; tr < 2; tr++)
            #pragma unroll
            for (int f = 0; f < 6; f++)
                #pragma unroll
                for (int j = 0; j < 4; j++) acc[tr][f][j] = 0ull;

        const float4* xq = (const float4*)(x + (size_t)b * CC * FIELD
                                             + (size_t)h * WW + col);
        float4 xb0 = xq[0];
        float4 xb1 = xq[1];

        #pragma unroll 4
        for (int c = 0; c < CC; c++) {
            float4 n0, n1;
            if (c < CC - 1) {
                n0 = xq[(size_t)(c + 1) * (FIELD / 4)];
                n1 = xq[(size_t)(c + 1) * (FIELD / 4) + 1];
            }
            u64 xx0 = pack2(xb0.x, xb0.y);
            u64 xx1 = pack2(xb0.z, xb0.w);
            u64 xx2 = pack2(xb1.x, xb1.y);
            u64 xx3 = pack2(xb1.z, xb1.w);
            #pragma unroll
            for (int tr = 0; tr < 2; tr++)
                #pragma unroll
                for (int f = 0; f < 6; f++) {
                    u64 al = c_al[((t0 + tr) * 6 + f) * CC + c];
                    acc[tr][f][0] = fma2(xx0, al, acc[tr][f][0]);
                    acc[tr][f][1] = fma2(xx1, al, acc[tr][f][1]);
                    acc[tr][f][2] = fma2(xx2, al, acc[tr][f][2]);
                    acc[tr][f][3] = fma2(xx3, al, acc[tr][f][3]);
                }
            if (c < CC - 1) { xb0 = n0; xb1 = n1; }
        }

        float* dst[6] = {g_w1, g_w2, g_w3, g_w1p, g_w2p, g_w3p};
        #pragma unroll
        for (int tr = 0; tr < 2; tr++) {
            const size_t base = (size_t)(bt0 + tr) * FIELD + (size_t)h * WW + col;
            #pragma unroll
            for (int f = 0; f < 6; f++) {
                float2 v0 = unpack2(acc[tr][f][0]);
                float2 v1 = unpack2(acc[tr][f][1]);
                float2 v2 = unpack2(acc[tr][f][2]);
                float2 v3 = unpack2(acc[tr][f][3]);
                *(float4*)&dst[f][base]     = make_float4(v0.x, v0.y, v1.x, v1.y);
                *(float4*)&dst[f][base + 4] = make_float4(v2.x, v2.y, v3.x, v3.y);
            }
        }
    }
}

// =====================================================================
// K2: bottom-up. One warp per (halfchunk,t,b) = 4096 warps, 8 rows each.
//   v2 = w2 * SW(w3); gv2 = rev-excl-w-scan(v2) (stored)
//   cherry = w1p * SW(w3p) * SE(w2p) -> out
// =====================================================================
__global__ void __launch_bounds__(128) k2_bottomup(float* __restrict__ out)
{
    const int wid  = threadIdx.x >> 5;
    const int lane = threadIdx.x & 31;
    const int gw   = blockIdx.x * 4 + wid;      // 4096 warps
    const int half =  gw        & 31;
    const int t    = (gw >> 5)  & 7;
    const int b    =  gw >> 8;
    const int bt   = b * T2 + t;
    const int col  = lane * 8;

    float s[3][8];
    #pragma unroll
    for (int k = 0; k < 3; k++)
        #pragma unroll
        for (int i = 0; i < 8; i++) s[k][i] = 0.f;

    for (int j = half + 1; j < NHC; j++) {
        #pragma unroll
        for (int k = 0; k < 3; k++) {
            const float* R = g_Sh + (((size_t)bt * 3 + k) * NHC + j) * WW + col;
            float4 q0 = *(const float4*)R, q1 = *(const float4*)(R + 4);
            s[k][0] += q0.x; s[k][1] += q0.y; s[k][2] += q0.z; s[k][3] += q0.w;
            s[k][4] += q1.x; s[k][5] += q1.y; s[k][6] += q1.z; s[k][7] += q1.w;
        }
    }

    float a3[8], p3[8], p2[8], incl[8];
    {
        wscan8(s[0], incl);
        #pragma unroll
        for (int i = 0; i < 8; i++) a3[i] = incl[i] - s[0][i];
        wscan8(s[1], incl);
        #pragma unroll
        for (int i = 0; i < 8; i++) p3[i] = incl[i] - s[1][i];
        float tot = wscan8(s[2], incl);
        #pragma unroll
        for (int i = 0; i < 8; i++) p2[i] = tot - incl[i];
    }

    float cssum[8];
    #pragma unroll
    for (int i = 0; i < 8; i++) cssum[i] = 0.f;

    #pragma unroll 1
    for (int r = 7; r >= 0; r--) {
        const int h = half * 8 + r;
        const size_t base = (size_t)bt * FIELD + (size_t)h * WW + col;

        float w2v[8]; LD8(w2v, g_w2 + base);
        float v2[8];
        #pragma unroll
        for (int i = 0; i < 8; i++) v2[i] = w2v[i] * a3[i];
        float tot = wscan8(v2, incl);
        float gv[8];
        #pragma unroll
        for (int i = 0; i < 8; i++) { gv[i] = tot - incl[i]; cssum[i] += gv[i]; }
        ST8(g_gv2 + base, gv);

        float w1pv[8]; LD8(w1pv, g_w1p + base);
        float ch[8];
        #pragma unroll
        for (int i = 0; i < 8; i++) ch[i] = w1pv[i] * p3[i] * p2[i];
        ST8(out + ((size_t)(b * NT + T2 + t)) * FIELD + (size_t)h * WW + col, ch);

        float w3v[8]; LD8(w3v, g_w3 + base);
        wscan8(w3v, incl);
        #pragma unroll
        for (int i = 0; i < 8; i++) a3[i] += incl[i] - w3v[i];

        float w3pv[8]; LD8(w3pv, g_w3p + base);
        wscan8(w3pv, incl);
        #pragma unroll
        for (int i = 0; i < 8; i++) p3[i] += incl[i] - w3pv[i];

        float w2pv[8]; LD8(w2pv, g_w2p + base);
        tot = wscan8(w2pv, incl);
        #pragma unroll
        for (int i = 0; i < 8; i++) p2[i] += tot - incl[i];
    }

    ST8(g_S3 + ((size_t)bt * NHC + half) * WW + col, cssum);
}

// =====================================================================
// KD: top-down. linear = w1 * strict-north colsum of gv2.
// One warp per (halfchunk,t,b); double-buffered row prefetch.
// =====================================================================
__global__ void __launch_bounds__(128) kD_topdown(float* __restrict__ out)
{
    const int wid  = threadIdx.x >> 5;
    const int lane = threadIdx.x & 31;
    const int gw   = blockIdx.x * 4 + wid;
    const int half =  gw        & 31;
    const int t    = (gw >> 5)  & 7;
    const int b    =  gw >> 8;
    const int bt   = b * T2 + t;
    const int col  = lane * 8;

    float va[8];
    #pragma unroll
    for (int i = 0; i < 8; i++) va[i] = 0.f;
    for (int j = 0; j < half; j++) {
        const float* p = g_S3 + ((size_t)bt * NHC + j) * WW + col;
        float4 a = *(const float4*)p, bq = *(const float4*)(p + 4);
        va[0] += a.x;  va[1] += a.y;  va[2] += a.z;  va[3] += a.w;
        va[4] += bq.x; va[5] += bq.y; va[6] += bq.z; va[7] += bq.w;
    }

    const size_t fbase = (size_t)bt * FIELD + (size_t)(half * 8) * WW + col;
    const size_t obase = ((size_t)(b * NT + t)) * FIELD + (size_t)(half * 8) * WW + col;

    float w1b[8], gvb[8];
    LD8(w1b, g_w1 + fbase);
    LD8(gvb, g_gv2 + fbase);

    #pragma unroll
    for (int r = 0; r < 8; r++) {
        float w1n[8], gvn[8];
        if (r < 7) {
            LD8(w1n, g_w1  + fbase + (size_t)(r + 1) * WW);
            LD8(gvn, g_gv2 + fbase + (size_t)(r + 1) * WW);
        }
        float o[8];
        #pragma unroll
        for (int i = 0; i < 8; i++) o[i] = w1b[i] * va[i];
        ST8(out + obase + (size_t)r * WW, o);
        #pragma unroll
        for (int i = 0; i < 8; i++) va[i] += gvb[i];
        if (r < 7) {
            #pragma unroll
            for (int i = 0; i < 8; i++) { w1b[i] = w1n[i]; gvb[i] = gvn[i]; }
        }
    }
}

// =====================================================================
extern "C" void kernel_launch(void* const* d_in, const int* in_sizes, int n_in,
                              void* d_out, int out_size)
{
    const float* x   = (const float*)d_in[0];
    const float* a1  = (const float*)d_in[1];
    const float* a2  = (const float*)d_in[2];
    const float* a3  = (const float*)d_in[3];
    const float* a1p = (const float*)d_in[4];
    const float* a2p = (const float*)d_in[5];
    const float* a3p = (const float*)d_in[6];
    float* out = (float*)d_out;

    k0_pack<<<6, 256>>>(a1, a2, a3, a1p, a2p, a3p);

    void* src = nullptr; void* dst = nullptr;
    cudaGetSymbolAddress(&src, g_apk);
    cudaGetSymbolAddress(&dst, c_al);
    cudaMemcpyAsync(dst, src, sizeof(u64) * T2 * 6 * CC,
                    cudaMemcpyDeviceToDevice, 0);

    dim3 gAB(NHC, BB);                    // (32, 16)
    kAB_colsum<<<gAB, 128>>>(x);

    dim3 g1(T2 / 2, NHC, BB);             // (4, 32, 16) = 2048 CTAs
    k1_weight<<<g1, 128>>>(x);

    k2_bottomup<<<BT * NHC / 4, 128>>>(out);   // 1024 blocks, 4096 warps
    kD_topdown <<<BT * NHC / 4, 128>>>(out);
}

// round 8
// speedup vs baseline: 2.1580x; 1.1633x over previous
#include <cuda_runtime.h>
#include <cstdint>

#define BB   16
#define CC   32
#define HH   256
#define WW   256
#define T2   8
#define NT   16
#define NQC  64               // quarter-chunks (4 rows each)
#define FIELD (HH*WW)
#define BT   (BB*T2)

typedef unsigned long long u64;

// ---------------- scratch (no cudaMalloc allowed) ----------------
__device__ __align__(256) float g_w1 [BT*FIELD];
__device__ __align__(256) float g_gv2[BT*FIELD];
__device__ __align__(256) float g_Sh [BT*3*NQC*WW];   // qc colsums (w3,w3p,w2p) -> suffix-excl after kS
__device__ __align__(256) float g_S3 [BT*NQC*WW];     // qc colsums of gv2 -> prefix-excl after kS2
__device__ u64 g_apk[T2*6*CC];                        // packed alphas

// ---------------- f32x2 helpers ----------------
__device__ __forceinline__ u64 fma2(u64 a, u64 b, u64 c) {
    u64 d; asm("fma.rn.f32x2 %0, %1, %2, %3;" : "=l"(d) : "l"(a), "l"(b), "l"(c)); return d;
}
__device__ __forceinline__ u64 add2(u64 a, u64 b) {
    u64 d; asm("add.rn.f32x2 %0, %1, %2;" : "=l"(d) : "l"(a), "l"(b)); return d;
}
__device__ __forceinline__ u64 pack2(float lo, float hi) {
    u64 r; asm("mov.b64 %0, {%1, %2};" : "=l"(r) : "f"(lo), "f"(hi)); return r;
}
__device__ __forceinline__ float2 unpack2(u64 v) {
    float2 f; asm("mov.b64 {%0, %1}, %2;" : "=f"(f.x), "=f"(f.y) : "l"(v)); return f;
}
__device__ __forceinline__ void LD8(float* v, const float* p) {
    float4 a = *(const float4*)p, b = *(const float4*)(p + 4);
    v[0]=a.x; v[1]=a.y; v[2]=a.z; v[3]=a.w; v[4]=b.x; v[5]=b.y; v[6]=b.z; v[7]=b.w;
}
__device__ __forceinline__ void ST8(float* p, const float* v) {
    *(float4*)p       = make_float4(v[0],v[1],v[2],v[3]);
    *(float4*)(p + 4) = make_float4(v[4],v[5],v[6],v[7]);
}

// ---------------- batched 64-lane scan (2 warps, 4 elems/lane) ----------------
// For each scan s: exclLane[s] = exclusive sum of all elements in lanes < this
// lane (within the 64-lane rowgroup); grand[s] = total. Two CTA barriers.
template<int S>
__device__ __forceinline__ void scan_batch(float (*v)[4], float* exclLane, float* grand,
                                           float (*stot)[2], int lane, int wi)
{
    float wsum[S], wincl[S];
    #pragma unroll
    for (int s = 0; s < S; s++) {
        float r = v[s][0] + v[s][1] + v[s][2] + v[s][3];
        float xx = r;
        #pragma unroll
        for (int d = 1; d < 32; d <<= 1) {
            float n = __shfl_up_sync(0xffffffffu, xx, d);
            if (lane >= d) xx += n;
        }
        wsum[s] = r; wincl[s] = xx;
    }
    if (lane == 31) {
        #pragma unroll
        for (int s = 0; s < S; s++) stot[s][wi] = wincl[s];
    }
    __syncthreads();
    #pragma unroll
    for (int s = 0; s < S; s++) {
        float t0 = stot[s][0], t1 = stot[s][1];
        exclLane[s] = (wi ? t0 : 0.f) + (wincl[s] - wsum[s]);
        grand[s]    = t0 + t1;
    }
    __syncthreads();
}

// =====================================================================
// K0: pack alphas duplicated into f32x2 pairs
// field order: 0=a1 1=a2 2=a3 3=a1p 4=a2p 5=a3p
// =====================================================================
__global__ void k0_pack(const float* __restrict__ a1,  const float* __restrict__ a2,
                        const float* __restrict__ a3,  const float* __restrict__ a1p,
                        const float* __restrict__ a2p, const float* __restrict__ a3p)
{
    int i = blockIdx.x * 256 + threadIdx.x;          // T2*6*CC = 1536
    if (i >= T2 * 6 * CC) return;
    int c = i % CC, f = (i / CC) % 6, t = i / (6 * CC);
    const float* p = (f == 0) ? a1 : (f == 1) ? a2 : (f == 2) ? a3
                   : (f == 3) ? a1p : (f == 4) ? a2p : a3p;
    float v = p[t * CC + c];
    g_apk[(t * 6 + f) * CC + c] = pack2(v, v);
}

// =====================================================================
// KAB: raw quarterchunk colsums contracted with alphas (all 8 trees).
// grid = (NQC, BB), 128 thr, 2 cols/thread.
// =====================================================================
__global__ void __launch_bounds__(128) kAB_colsum(const float* __restrict__ x)
{
    __shared__ __align__(16) u64 s_alB[CC][24];   // slot = k*8 + t
    const int tid = threadIdx.x;
    const int qc  = blockIdx.x;
    const int b   = blockIdx.y;
    const int wc  = tid * 2;

    for (int i = tid; i < CC * 24; i += 128) {
        int slot = i % 24, c = i / 24;
        int k = slot / 8, t = slot % 8;
        int f = (k == 0) ? 2 : (k == 1) ? 5 : 4;   // a3, a3p, a2p
        s_alB[c][slot] = g_apk[(t * 6 + f) * CC + c];
    }
    __syncthreads();

    u64 acc[24];
    #pragma unroll
    for (int s = 0; s < 24; s++) acc[s] = 0ull;

    #pragma unroll 2
    for (int c = 0; c < CC; c++) {
        const float2* xp = (const float2*)(x
            + ((size_t)(b * CC + c) * HH + qc * 4) * WW + wc);
        u64 sum = 0ull;
        #pragma unroll
        for (int r = 0; r < 4; r++) {
            float2 v = xp[r * (WW / 2)];
            sum = add2(sum, pack2(v.x, v.y));
        }
        #pragma unroll
        for (int j = 0; j < 12; j++) {
            ulonglong2 p = *(const ulonglong2*)&s_alB[c][2 * j];
            acc[2*j]   = fma2(sum, p.x, acc[2*j]);
            acc[2*j+1] = fma2(sum, p.y, acc[2*j+1]);
        }
    }

    #pragma unroll
    for (int k = 0; k < 3; k++)
        #pragma unroll
        for (int t = 0; t < T2; t++) {
            float2 v = unpack2(acc[k * 8 + t]);
            size_t o = (((size_t)(b * T2 + t) * 3 + k) * NQC + qc) * WW + wc;
            *(float2*)&g_Sh[o] = v;
        }
}

// =====================================================================
// KS: in-place exclusive SUFFIX sum of g_Sh along qc (per bt,k,w column)
// =====================================================================
__global__ void kS_suffix()
{
    int gid = blockIdx.x * 128 + threadIdx.x;   // BT*3*WW = 98304
    int w   = gid & (WW - 1);
    int ktb = gid >> 8;                         // 0..383
    float* base = g_Sh + (size_t)ktb * NQC * WW + w;
    float v[NQC];
    #pragma unroll
    for (int j = 0; j < NQC; j++) v[j] = base[(size_t)j * WW];
    float s = 0.f;
    #pragma unroll
    for (int j = NQC - 1; j >= 0; j--) {
        base[(size_t)j * WW] = s;
        s += v[j];
    }
}

// =====================================================================
// KS2: in-place exclusive PREFIX sum of g_S3 along qc
// =====================================================================
__global__ void kS2_prefix()
{
    int gid = blockIdx.x * 128 + threadIdx.x;   // BT*WW = 32768
    int w   = gid & (WW - 1);
    int bt  = gid >> 8;
    float* base = g_S3 + (size_t)bt * NQC * WW + w;
    float v[NQC];
    #pragma unroll
    for (int j = 0; j < NQC; j++) v[j] = base[(size_t)j * WW];
    float s = 0.f;
    #pragma unroll
    for (int j = 0; j < NQC; j++) {
        base[(size_t)j * WW] = s;
        s += v[j];
    }
}

// =====================================================================
// K1_FUSED: weighting GEMM + bottom-up pass, CTA-level.
// CTA = (tree-pair, halfchunk, b). 128 thr = 2 rowgroups x 64 lanes x 4 cols.
// Rowgroup rg owns quarterchunk qc = hc*2+rg (4 rows, bottom-up).
// Emits: cherry -> out, gv2, w1, S3(raw qc colsums of gv2).
// =====================================================================
__global__ void __launch_bounds__(128) k1_fused(const float* __restrict__ x,
                                                float* __restrict__ out)
{
    __shared__ __align__(16) u64 s_al[2][CC][6];
    __shared__ float s_tot[2][8][2];

    const int tid  = threadIdx.x;
    const int rg   = tid >> 6;
    const int l    = tid & 63;
    const int lane = tid & 31;
    const int wi   = (tid >> 5) & 1;
    const int col  = l * 4;
    const int t0   = blockIdx.x * 2;
    const int hc   = blockIdx.y;
    const int b    = blockIdx.z;
    const int bt0  = b * T2 + t0;
    const int qc   = hc * 2 + rg;

    for (int i = tid; i < 2 * 6 * CC; i += 128) {
        int c = i % CC, f = (i / CC) % 6, tr = i / (6 * CC);
        s_al[tr][c][f] = g_apk[((t0 + tr) * 6 + f) * CC + c];
    }
    __syncthreads();

    // ---- init states from suffix-excl Sh tables ----
    float st[8][4];
    #pragma unroll
    for (int tr = 0; tr < 2; tr++)
        #pragma unroll
        for (int k = 0; k < 3; k++) {
            float4 v = *(const float4*)&g_Sh[
                (((size_t)(bt0 + tr) * 3 + k) * NQC + qc) * WW + col];
            st[tr*3+k][0]=v.x; st[tr*3+k][1]=v.y; st[tr*3+k][2]=v.z; st[tr*3+k][3]=v.w;
        }
    float ex[8], gr[8];
    scan_batch<6>(st, ex, gr, s_tot[rg], lane, wi);

    float a3[2][4], p3[2][4], p2[2][4], cs[2][4];
    #pragma unroll
    for (int tr = 0; tr < 2; tr++) {
        float run;
        run = 0.f;
        #pragma unroll
        for (int i = 0; i < 4; i++) { a3[tr][i] = ex[tr*3+0] + run; run += st[tr*3+0][i]; }
        run = 0.f;
        #pragma unroll
        for (int i = 0; i < 4; i++) { p3[tr][i] = ex[tr*3+1] + run; run += st[tr*3+1][i]; }
        run = 0.f;
        #pragma unroll
        for (int i = 0; i < 4; i++) { run += st[tr*3+2][i]; p2[tr][i] = gr[tr*3+2] - (ex[tr*3+2] + run); }
        #pragma unroll
        for (int i = 0; i < 4; i++) cs[tr][i] = 0.f;
    }

    // ---- 4 rows, bottom-up ----
    #pragma unroll 1
    for (int r = 3; r >= 0; r--) {
        const int h = qc * 4 + r;

        // GEMM: 12 (tree,field) streams, 4 cols/thread
        u64 acc[2][6][2];
        #pragma unroll
        for (int tr = 0; tr < 2; tr++)
            #pragma unroll
            for (int f = 0; f < 6; f++) { acc[tr][f][0] = 0ull; acc[tr][f][1] = 0ull; }

        const float4* xq = (const float4*)(x + (size_t)b * CC * FIELD
                                             + (size_t)h * WW + col);
        float4 xb = xq[0];
        #pragma unroll 8
        for (int c = 0; c < CC; c++) {
            float4 nx;
            if (c < CC - 1) nx = xq[(size_t)(c + 1) * (FIELD / 4)];
            u64 x01 = pack2(xb.x, xb.y);
            u64 x23 = pack2(xb.z, xb.w);
            #pragma unroll
            for (int tr = 0; tr < 2; tr++) {
                ulonglong2 pA = *(const ulonglong2*)&s_al[tr][c][0];
                ulonglong2 pB = *(const ulonglong2*)&s_al[tr][c][2];
                ulonglong2 pC = *(const ulonglong2*)&s_al[tr][c][4];
                acc[tr][0][0] = fma2(x01, pA.x, acc[tr][0][0]);
                acc[tr][0][1] = fma2(x23, pA.x, acc[tr][0][1]);
                acc[tr][1][0] = fma2(x01, pA.y, acc[tr][1][0]);
                acc[tr][1][1] = fma2(x23, pA.y, acc[tr][1][1]);
                acc[tr][2][0] = fma2(x01, pB.x, acc[tr][2][0]);
                acc[tr][2][1] = fma2(x23, pB.x, acc[tr][2][1]);
                acc[tr][3][0] = fma2(x01, pB.y, acc[tr][3][0]);
                acc[tr][3][1] = fma2(x23, pB.y, acc[tr][3][1]);
                acc[tr][4][0] = fma2(x01, pC.x, acc[tr][4][0]);
                acc[tr][4][1] = fma2(x23, pC.x, acc[tr][4][1]);
                acc[tr][5][0] = fma2(x01, pC.y, acc[tr][5][0]);
                acc[tr][5][1] = fma2(x23, pC.y, acc[tr][5][1]);
            }
            if (c < CC - 1) xb = nx;
        }

        // stores that need only pre-update states: w1, cherry
        #pragma unroll
        for (int tr = 0; tr < 2; tr++) {
            const size_t ob = (size_t)(bt0 + tr) * FIELD + (size_t)h * WW + col;
            float2 w1a = unpack2(acc[tr][0][0]), w1b = unpack2(acc[tr][0][1]);
            *(float4*)&g_w1[ob] = make_float4(w1a.x, w1a.y, w1b.x, w1b.y);

            float2 pa = unpack2(acc[tr][3][0]), pb = unpack2(acc[tr][3][1]);
            float w1p[4] = {pa.x, pa.y, pb.x, pb.y};
            float ch[4];
            #pragma unroll
            for (int i = 0; i < 4; i++) ch[i] = w1p[i] * p3[tr][i] * p2[tr][i];
            *(float4*)&out[((size_t)(b * NT + T2 + t0 + tr)) * FIELD
                           + (size_t)h * WW + col] =
                make_float4(ch[0], ch[1], ch[2], ch[3]);
        }

        // batched scans: per tree {w3, w3p, w2p, v2}
        float sv[8][4];
        #pragma unroll
        for (int tr = 0; tr < 2; tr++) {
            float2 u0, u1;
            u0 = unpack2(acc[tr][2][0]); u1 = unpack2(acc[tr][2][1]);
            sv[tr*4+0][0]=u0.x; sv[tr*4+0][1]=u0.y; sv[tr*4+0][2]=u1.x; sv[tr*4+0][3]=u1.y;
            u0 = unpack2(acc[tr][5][0]); u1 = unpack2(acc[tr][5][1]);
            sv[tr*4+1][0]=u0.x; sv[tr*4+1][1]=u0.y; sv[tr*4+1][2]=u1.x; sv[tr*4+1][3]=u1.y;
            u0 = unpack2(acc[tr][4][0]); u1 = unpack2(acc[tr][4][1]);
            sv[tr*4+2][0]=u0.x; sv[tr*4+2][1]=u0.y; sv[tr*4+2][2]=u1.x; sv[tr*4+2][3]=u1.y;
            u0 = unpack2(acc[tr][1][0]); u1 = unpack2(acc[tr][1][1]);
            float w2v[4] = {u0.x, u0.y, u1.x, u1.y};
            #pragma unroll
            for (int i = 0; i < 4; i++) sv[tr*4+3][i] = w2v[i] * a3[tr][i];
        }
        scan_batch<8>(sv, ex, gr, s_tot[rg], lane, wi);

        #pragma unroll
        for (int tr = 0; tr < 2; tr++) {
            const size_t ob = (size_t)(bt0 + tr) * FIELD + (size_t)h * WW + col;
            float run, gv[4];
            // gv2 = rev-excl(v2); accumulate colsum
            run = 0.f;
            #pragma unroll
            for (int i = 0; i < 4; i++) {
                run += sv[tr*4+3][i];
                gv[i] = gr[tr*4+3] - (ex[tr*4+3] + run);
                cs[tr][i] += gv[i];
            }
            *(float4*)&g_gv2[ob] = make_float4(gv[0], gv[1], gv[2], gv[3]);
            // state updates
            run = 0.f;
            #pragma unroll
            for (int i = 0; i < 4; i++) { a3[tr][i] += ex[tr*4+0] + run; run += sv[tr*4+0][i]; }
            run = 0.f;
            #pragma unroll
            for (int i = 0; i < 4; i++) { p3[tr][i] += ex[tr*4+1] + run; run += sv[tr*4+1][i]; }
            run = 0.f;
            #pragma unroll
            for (int i = 0; i < 4; i++) { run += sv[tr*4+2][i]; p2[tr][i] += gr[tr*4+2] - (ex[tr*4+2] + run); }
        }
    }

    #pragma unroll
    for (int tr = 0; tr < 2; tr++) {
        size_t o = ((size_t)(bt0 + tr) * NQC + qc) * WW + col;
        *(float4*)&g_S3[o] = make_float4(cs[tr][0], cs[tr][1], cs[tr][2], cs[tr][3]);
    }
}

// =====================================================================
// KD: top-down. linear = w1 * strict-north colsum of gv2.
// One warp per (qc,t,b) = 8192 warps; init from prefix-excl S3.
// =====================================================================
__global__ void __launch_bounds__(128) kD_topdown(float* __restrict__ out)
{
    const int wid  = threadIdx.x >> 5;
    const int lane = threadIdx.x & 31;
    const int gw   = blockIdx.x * 4 + wid;
    const int qc   =  gw        & 63;
    const int t    = (gw >> 6)  & 7;
    const int b    =  gw >> 9;
    const int bt   = b * T2 + t;
    const int col  = lane * 8;

    float va[8];
    LD8(va, g_S3 + ((size_t)bt * NQC + qc) * WW + col);   // prefix-excl

    const size_t fbase = (size_t)bt * FIELD + (size_t)(qc * 4) * WW + col;
    const size_t obase = ((size_t)(b * NT + t)) * FIELD + (size_t)(qc * 4) * WW + col;

    float w1b[8], gvb[8];
    LD8(w1b, g_w1 + fbase);
    LD8(gvb, g_gv2 + fbase);

    #pragma unroll
    for (int r = 0; r < 4; r++) {
        float w1n[8], gvn[8];
        if (r < 3) {
            LD8(w1n, g_w1  + fbase + (size_t)(r + 1) * WW);
            LD8(gvn, g_gv2 + fbase + (size_t)(r + 1) * WW);
        }
        float o[8];
        #pragma unroll
        for (int i = 0; i < 8; i++) o[i] = w1b[i] * va[i];
        ST8(out + obase + (size_t)r * WW, o);
        #pragma unroll
        for (int i = 0; i < 8; i++) va[i] += gvb[i];
        if (r < 3) {
            #pragma unroll
            for (int i = 0; i < 8; i++) { w1b[i] = w1n[i]; gvb[i] = gvn[i]; }
        }
    }
}

// =====================================================================
extern "C" void kernel_launch(void* const* d_in, const int* in_sizes, int n_in,
                              void* d_out, int out_size)
{
    const float* x   = (const float*)d_in[0];
    const float* a1  = (const float*)d_in[1];
    const float* a2  = (const float*)d_in[2];
    const float* a3  = (const float*)d_in[3];
    const float* a1p = (const float*)d_in[4];
    const float* a2p = (const float*)d_in[5];
    const float* a3p = (const float*)d_in[6];
    float* out = (float*)d_out;

    k0_pack<<<6, 256>>>(a1, a2, a3, a1p, a2p, a3p);

    dim3 gAB(NQC, BB);                          // (64, 16)
    kAB_colsum<<<gAB, 128>>>(x);

    kS_suffix<<<BT * 3 * WW / 128, 128>>>();    // 768 blocks

    dim3 gC(T2 / 2, HH / 8, BB);                // (4, 32, 16) = 2048 CTAs
    k1_fused<<<gC, 128>>>(x, out);

    kS2_prefix<<<BT * WW / 128, 128>>>();       // 256 blocks

    kD_topdown<<<BT * NQC / 4, 128>>>(out);     // 2048 blocks
}